// round 8
// baseline (speedup 1.0000x reference)
#include <cuda_runtime.h>
#include <math.h>

#define MM 48
#define LL 48
#define NN 256
#define NPAIR 1176
#define NT 128            // CTA threads (phases A/B); zipper uses 64
#define ZL 64             // zipper lanes (2 warps)
#define ZPJ 19            // pairs per zipper lane (64*19 = 1216)
#define SLOTS (ZL * ZPJ)  // 1216
#define CPR 16            // checkpoint rows (sites l = 3b+2)

// smem floats: ab (2*2304) | cp (16*1216) | u (48) | prt (8)
#define SM_AB  0
#define SM_CP  (2 * LL * MM)
#define SM_U   (SM_CP + CPR * SLOTS)
#define SM_PRT (SM_U + LL)
#define SMEMF  (SM_PRT + 8)

typedef unsigned long long u64;

// Blackwell packed f32x2 helpers (one FMA-pipe op for two lanes)
__device__ __forceinline__ u64 f2mul(u64 a, u64 b) {
    u64 r; asm("mul.rn.f32x2 %0,%1,%2;" : "=l"(r) : "l"(a), "l"(b)); return r;
}
__device__ __forceinline__ u64 f2fma(u64 a, u64 b, u64 c) {
    u64 r; asm("fma.rn.f32x2 %0,%1,%2,%3;" : "=l"(r) : "l"(a), "l"(b), "l"(c)); return r;
}
__device__ __forceinline__ u64 f2add(u64 a, u64 b) {
    u64 r; asm("add.rn.f32x2 %0,%1,%2;" : "=l"(r) : "l"(a), "l"(b)); return r;
}
__device__ __forceinline__ u64 f2pack(float x, float y) {
    u64 r; asm("mov.b64 %0,{%1,%2};" : "=l"(r) : "f"(x), "f"(y)); return r;
}
__device__ __forceinline__ void f2unpack(u64 v, float& x, float& y) {
    asm("mov.b64 {%0,%1},%2;" : "=f"(x), "=f"(y) : "l"(v));
}

// Accurate f32 sincos: Cody-Waite FMA range reduction + Taylor polys.
__device__ __forceinline__ void sincos_acc(float x, float* s, float* c) {
    float kf = rintf(x * 0.63661977236758134f);
    int k = (int)kf;
    float r = fmaf(kf, -1.57079637050628662109375f, x);
    r = fmaf(kf, 4.37113882867379290e-8f, r);
    float r2 = r * r;
    float ps = fmaf(r2, 2.7557314297e-06f, -1.9841270114e-04f);
    ps = fmaf(r2, ps, 8.3333337680e-03f);
    ps = fmaf(r2, ps, -1.6666667163e-01f);
    float sr = fmaf(r * r2, ps, r);
    float pc = fmaf(r2, -2.7557314297e-07f, 2.4760126951e-05f);
    pc = fmaf(r2, pc, -1.3888889225e-03f);
    pc = fmaf(r2, pc, 4.1666667908e-02f);
    float cr = fmaf(r2 * r2, pc, fmaf(r2, -0.5f, 1.0f));
    switch (k & 3) {
        case 0: *s = sr;  *c = cr;  break;
        case 1: *s = cr;  *c = -sr; break;
        case 2: *s = -sr; *c = -cr; break;
        default:*s = -cr; *c = sr;  break;
    }
}

__global__ __launch_bounds__(NT, 1) void fused_kernel(
    const float* __restrict__ inp,      // (N,L)
    const float* __restrict__ theta,    // (L,M)
    const float* __restrict__ coef,     // (M,)
    const float* __restrict__ rand_u,   // (L,N)
    float* __restrict__ out)            // N*L bits then N probs
{
    extern __shared__ float sm[];
    float2* ab  = reinterpret_cast<float2*>(sm + SM_AB);
    float*  cp  = sm + SM_CP;
    float*  ush = sm + SM_U;
    float*  prt = sm + SM_PRT;

    const int n = blockIdx.x, tid = threadIdx.x;

    // ---- Phase A: embedding tile (all 128 threads) ----
    const float PI2F = 1.57079637050628662109375f;
#pragma unroll
    for (int e = tid; e < LL * MM; e += NT) {
        int l = e / MM, m = e % MM;
        float ang = inp[n * LL + l] * ((float)(m + 1) * PI2F);
        float sa, ca; sincos_acc(ang, &sa, &ca);
        float st, ct; sincos_acc(theta[e], &st, &ct);
        float cf = coef[m];
        ab[e] = make_float2(cf * (ct * ca - st * sa),
                            cf * (st * ca + ct * sa));
    }
    if (tid < LL) ush[tid] = rand_u[tid * NN + n];
    __syncthreads();

    // ---- Phase B: backward scan, checkpoint SUF (w baked in) every 3rd site ----
    {
        int bm[10], bk[10]; float run[10];
#pragma unroll
        for (int q = 0; q < 10; q++) {
            int s = tid + NT * q;
            bm[q] = 0; bk[q] = 0; run[q] = 0.0f;
            if (s < NPAIR) {
                int m = 0, off = 0;
                while (off + (MM - m) <= s) { off += MM - m; m++; }
                bm[q] = m; bk[q] = m + (s - off);
                run[q] = (bm[q] == bk[q]) ? 1.0f : 2.0f;
            }
        }
        for (int l = LL - 1; l >= 0; l--) {
            if ((l % 3) == 2) {
                int row = l / 3;
#pragma unroll
                for (int q = 0; q < 10; q++) {
                    int s = tid + NT * q;
                    if (s < SLOTS) cp[row * SLOTS + s] = run[q];
                }
            }
            const float2* abl = ab + l * MM;
#pragma unroll
            for (int q = 0; q < 10; q++) {
                float2 vm = abl[bm[q]], vk = abl[bk[q]];
                run[q] *= fmaf(vm.x, vk.x, vm.y * vk.y);
            }
        }
    }
    __syncthreads();
    if (tid >= ZL) return;   // warps 2,3 done; zipper = 64 threads

    const int lane = tid & 31, zw = tid >> 5;

    // ---- pair decode: 19 contiguous row-major triangle pairs per lane ----
    int pmk[ZPJ]; float P[ZPJ];
    {
        int p0 = tid * ZPJ;
        int pc = (p0 < NPAIR) ? p0 : (NPAIR - 1);
        int m = 0, off = 0;
        while (off + (MM - m) <= pc) { off += MM - m; m++; }
        int k = m + (pc - off);
#pragma unroll
        for (int j = 0; j < ZPJ; j++) {
            pmk[j] = m | (k << 8);
            P[j] = (p0 + j < NPAIR) ? 1.0f : 0.0f;
            if (++k == MM) { ++m; k = m; }
            if (m >= MM) { m = MM - 1; k = MM - 1; }
        }
    }

    // packed (aa,bb) for pair j at site l
    auto ldp2 = [&](int l, int j) -> u64 {
        int mk = pmk[j];
        u64 vm = *reinterpret_cast<const u64*>(&ab[l * MM + (mk & 0xFF)]);
        u64 vk = *reinterpret_cast<const u64*>(&ab[l * MM + (mk >> 8)]);
        return f2mul(vm, vk);
    };

    // initial SUF rows for block 0: Y=SUF(1), sufc=SUF(0)
    float sufc[ZPJ], Ysuf[ZPJ];
#pragma unroll
    for (int j = 0; j < ZPJ; j++) {
        float cpv = cp[tid * ZPJ + j];            // SUF(2)
        float aa, bb;
        f2unpack(ldp2(2, j), aa, bb);
        Ysuf[j] = cpv * (aa + bb);
        f2unpack(ldp2(1, j), aa, bb);
        sufc[j] = Ysuf[j] * (aa + bb);
    }
    float ucur = ush[0];
    float denom0 = 1.0f;
    int Kexp = 0;
    u64 bits = 0ull;

#pragma unroll 1
    for (int b = 0; b < CPR; b++) {
#pragma unroll
        for (int li = 0; li < 3; li++) {
            const int l = 3 * b + li;

            // accumulation + speculative P01 = P*(aa,bb), all pre-reduction
            u64 P01[ZPJ];
            u64 acc0 = 0ull, acc1 = 0ull;
#pragma unroll
            for (int j = 0; j < ZPJ; j++) {
                u64 prod2 = ldp2(l, j);
                float ps = P[j] * sufc[j];
                if (j & 1) acc1 = f2fma(f2pack(ps, ps), prod2, acc1);
                else       acc0 = f2fma(f2pack(ps, ps), prod2, acc0);
                P01[j] = f2mul(f2pack(P[j], P[j]), prod2);
            }
            float s0, s1;
            f2unpack(f2add(acc0, acc1), s0, s1);
#pragma unroll
            for (int o = 16; o; o >>= 1) {
                s0 += __shfl_xor_sync(0xffffffffu, s0, o);
                s1 += __shfl_xor_sync(0xffffffffu, s1, o);
            }
            const int par = l & 1;
            if (lane == 0) { prt[par * 4 + zw] = s0; prt[par * 4 + 2 + zw] = s1; }

            // window: prepare NEXT step's suffix + u (bit-independent, fills bar wait)
            float unxt = ucur;
            if (li == 0) {
#pragma unroll
                for (int j = 0; j < ZPJ; j++) sufc[j] = Ysuf[j];
                unxt = ush[l + 1];
            } else if (li == 1) {
#pragma unroll
                for (int j = 0; j < ZPJ; j++) sufc[j] = cp[b * SLOTS + tid * ZPJ + j];
                unxt = ush[l + 1];
            } else if (b + 1 < CPR) {
#pragma unroll
                for (int j = 0; j < ZPJ; j++) {
                    float cpv = cp[(b + 1) * SLOTS + tid * ZPJ + j];  // SUF(3b+5)
                    float aa, bb;
                    f2unpack(ldp2(3 * b + 5, j), aa, bb);
                    Ysuf[j] = cpv * (aa + bb);                        // SUF(3b+4)
                    f2unpack(ldp2(3 * b + 4, j), aa, bb);
                    sufc[j] = Ysuf[j] * (aa + bb);                    // SUF(3b+3)
                }
                unxt = ush[l + 1];
            }

            asm volatile("bar.sync 1, 64;" ::: "memory");

            // redundant decision on all 64 threads (identical values)
            float S0 = prt[par * 4 + 0] + prt[par * 4 + 1];
            float S1 = prt[par * 4 + 2] + prt[par * 4 + 3];
            float den = fabsf(S0 + S1);
            int bit = (ucur * den < fabsf(S1)) ? 1 : 0;   // u < |S1|/den
            if (l == 0) denom0 = den;
            int eb = (__float_as_int(den) >> 23) & 0xFF;  // exact 2^-k renorm
            int kk = eb ? (eb - 127) >> 1 : 0;
            Kexp += kk;
            float scale = __int_as_float((127 - kk) << 23);
            bits |= (u64)bit << l;
#pragma unroll
            for (int j = 0; j < ZPJ; j++) {               // select + scale only
                float lo, hi;
                f2unpack(P01[j], lo, hi);
                P[j] = (bit ? hi : lo) * scale;
            }
            ucur = unxt;
        }
    }

    // ---- epilogue: final inner = sum w*P (true value * 2^Kexp), outputs ----
    float sf = 0.0f;
#pragma unroll
    for (int j = 0; j < ZPJ; j++) {
        int mk = pmk[j];
        sf += (((mk & 0xFF) == (mk >> 8)) ? 1.0f : 2.0f) * P[j];   // pads: P=0
    }
#pragma unroll
    for (int o = 16; o; o >>= 1) sf += __shfl_xor_sync(0xffffffffu, sf, o);
    if (lane == 0) prt[zw] = sf;
    asm volatile("bar.sync 1, 64;" ::: "memory");

    if (tid < LL) out[n * LL + tid] = (float)((bits >> tid) & 1ull);
    if (tid == 0) {
        double Sf = (double)(prt[0] + prt[1]);
        double pmv = ldexp(fabs(Sf), Kexp) / (double)denom0;
        out[NN * LL + n] = (float)pmv;
    }
}

extern "C" void kernel_launch(void* const* d_in, const int* in_sizes, int n_in,
                              void* d_out, int out_size) {
    const float* inp    = (const float*)d_in[0];   // (N,L)
    const float* theta  = (const float*)d_in[1];   // (L,M)
    const float* coef   = (const float*)d_in[2];   // (M,)
    const float* rand_u = (const float*)d_in[3];   // (L,N)
    float* out = (float*)d_out;

    static int smem_set = 0;
    if (!smem_set) {
        cudaFuncSetAttribute(fused_kernel,
                             cudaFuncAttributeMaxDynamicSharedMemorySize,
                             SMEMF * (int)sizeof(float));
        smem_set = 1;
    }
    fused_kernel<<<NN, NT, SMEMF * sizeof(float)>>>(inp, theta, coef, rand_u, out);
}